// round 15
// baseline (speedup 1.0000x reference)
#include <cuda_runtime.h>
#include <cuda_bf16.h>
#include <math.h>
#include <stdint.h>

#define BATCH  4
#define NQ     1024
#define NK     1024
#define DMODEL 512
#define NHEAD  8
#define DHEAD  64
#define LN_EPS 1e-5f

#define KSPLIT 4  // ctx split-K factor

// ---------------- scratch (device globals: allocation-free) ----------------
__device__ float g_Q[(size_t)BATCH * NQ * DMODEL];
__device__ float g_K[(size_t)BATCH * NK * DMODEL];
__device__ float g_V[(size_t)BATCH * NK * DMODEL];
__device__ float g_ctx[(size_t)BATCH * NQ * DMODEL];
__device__ float g_ctx_part[(size_t)KSPLIT * BATCH * NQ * DMODEL];
__device__ float g_x[(size_t)BATCH * NQ * DMODEL];
__device__ float g_w_fb[(size_t)BATCH * NHEAD * NQ * NK];

// bf16 hi/lo split buffers (reused: input split -> then Q/K split)
__device__ __align__(256) __nv_bfloat16 g_qx_hi[(size_t)BATCH * NQ * DMODEL];
__device__ __align__(256) __nv_bfloat16 g_qx_lo[(size_t)BATCH * NQ * DMODEL];
__device__ __align__(256) __nv_bfloat16 g_kx_hi[(size_t)BATCH * NK * DMODEL];
__device__ __align__(256) __nv_bfloat16 g_kx_lo[(size_t)BATCH * NK * DMODEL];
__device__ __align__(256) __nv_bfloat16 g_cx_hi[(size_t)BATCH * NQ * DMODEL];
__device__ __align__(256) __nv_bfloat16 g_cx_lo[(size_t)BATCH * NQ * DMODEL];
// transposed+split weights: [mat 0..3 = q,k,v,o][hi=0,lo=1][N=512][K=512]
__device__ __align__(256) __nv_bfloat16 g_wt[4][2][(size_t)DMODEL * DMODEL];

// ================= warp-MMA primitives (base ISA) ==========================
__device__ __forceinline__ uint32_t smem_u32_of(const void* p) {
    uint32_t a;
    asm("{ .reg .u64 t; cvta.to.shared.u64 t, %1; cvt.u32.u64 %0, t; }"
        : "=r"(a) : "l"(p));
    return a;
}
__device__ __forceinline__ void ldsm_x4(uint32_t& r0, uint32_t& r1,
                                        uint32_t& r2, uint32_t& r3, uint32_t a) {
    asm volatile("ldmatrix.sync.aligned.m8n8.x4.shared.b16 {%0,%1,%2,%3}, [%4];"
                 : "=r"(r0), "=r"(r1), "=r"(r2), "=r"(r3) : "r"(a));
}
__device__ __forceinline__ void ldsm_x2(uint32_t& r0, uint32_t& r1, uint32_t a) {
    asm volatile("ldmatrix.sync.aligned.m8n8.x2.shared.b16 {%0,%1}, [%2];"
                 : "=r"(r0), "=r"(r1) : "r"(a));
}
__device__ __forceinline__ void ldsm_x2_trans(uint32_t& r0, uint32_t& r1, uint32_t a) {
    asm volatile("ldmatrix.sync.aligned.m8n8.x2.trans.shared.b16 {%0,%1}, [%2];"
                 : "=r"(r0), "=r"(r1) : "r"(a));
}
__device__ __forceinline__ void mma_bf16(float* c, const uint32_t* a, const uint32_t* b) {
    asm volatile(
        "mma.sync.aligned.m16n8k16.row.col.f32.bf16.bf16.f32 "
        "{%0,%1,%2,%3}, {%4,%5,%6,%7}, {%8,%9}, {%0,%1,%2,%3};"
        : "+f"(c[0]), "+f"(c[1]), "+f"(c[2]), "+f"(c[3])
        : "r"(a[0]), "r"(a[1]), "r"(a[2]), "r"(a[3]), "r"(b[0]), "r"(b[1]));
}
__device__ __forceinline__ uint32_t pack_bf2(__nv_bfloat16 x, __nv_bfloat16 y) {
    return (uint32_t)__bfloat16_as_ushort(x) |
           ((uint32_t)__bfloat16_as_ushort(y) << 16);
}
__device__ __forceinline__ void split2(float x, float y, uint32_t& hi, uint32_t& lo) {
    __nv_bfloat16 hx = __float2bfloat16(x), hy = __float2bfloat16(y);
    __nv_bfloat16 lx = __float2bfloat16(x - __bfloat162float(hx));
    __nv_bfloat16 ly = __float2bfloat16(y - __bfloat162float(hy));
    hi = pack_bf2(hx, hy);
    lo = pack_bf2(lx, ly);
}

// ============== projection GEMM (unchanged from R10) =======================
#define RS    20
#define W_AHI 0
#define W_ALO (128 * RS)
#define W_BHI (2 * 128 * RS)
#define W_BLO (3 * 128 * RS)

__device__ __forceinline__ void gemm_mma_body(
    const __nv_bfloat16* __restrict__ Ahi, const __nv_bfloat16* __restrict__ Alo,
    const __nv_bfloat16* __restrict__ Bhi, const __nv_bfloat16* __restrict__ Blo,
    const float* __restrict__ bias, float* __restrict__ C)
{
    __shared__ uint32_t smw[4 * 128 * RS];
    const uint32_t smb = smem_u32_of(smw);
    const int tid  = threadIdx.x;
    const int wid  = tid >> 5, lane = tid & 31;
    const int row0 = blockIdx.y * 128;
    const int col0 = blockIdx.x * 128;
    const int m0   = (wid >> 2) * 64;
    const int n0   = (wid & 3) * 32;

    const int aRow  = lane & 15;
    const int aHalf = (lane >> 4) << 2;
    const int bRow  = lane & 7;
    const int bHalf = ((lane >> 3) & 1) << 2;

    float acc[4][4][4];
    #pragma unroll
    for (int mt = 0; mt < 4; mt++)
        #pragma unroll
        for (int nt = 0; nt < 4; nt++)
            #pragma unroll
            for (int e = 0; e < 4; e++) acc[mt][nt][e] = 0.f;

    for (int ks = 0; ks < DMODEL; ks += 32) {
        if (ks) __syncthreads();
        #pragma unroll
        for (int i = 0; i < 2; i++) {
            int idx = tid + i * 256;
            int r = idx >> 2, c = idx & 3;
            *reinterpret_cast<uint4*>(&smw[W_AHI + r * RS + c * 4]) =
                *reinterpret_cast<const uint4*>(Ahi + (size_t)(row0 + r) * DMODEL + ks + c * 8);
            *reinterpret_cast<uint4*>(&smw[W_ALO + r * RS + c * 4]) =
                *reinterpret_cast<const uint4*>(Alo + (size_t)(row0 + r) * DMODEL + ks + c * 8);
            *reinterpret_cast<uint4*>(&smw[W_BHI + r * RS + c * 4]) =
                *reinterpret_cast<const uint4*>(Bhi + (size_t)(col0 + r) * DMODEL + ks + c * 8);
            *reinterpret_cast<uint4*>(&smw[W_BLO + r * RS + c * 4]) =
                *reinterpret_cast<const uint4*>(Blo + (size_t)(col0 + r) * DMODEL + ks + c * 8);
        }
        __syncthreads();

        #pragma unroll
        for (int kk = 0; kk < 2; kk++) {
            const int kw = kk * 8;
            uint32_t ah[4][4], al[4][4], bh[4][2], bl[4][2];
            #pragma unroll
            for (int mt = 0; mt < 4; mt++) {
                uint32_t addr = smb + 4 * (W_AHI + (m0 + mt * 16 + aRow) * RS + kw + aHalf);
                ldsm_x4(ah[mt][0], ah[mt][1], ah[mt][2], ah[mt][3], addr);
                ldsm_x4(al[mt][0], al[mt][1], al[mt][2], al[mt][3],
                        addr + 4 * (W_ALO - W_AHI));
            }
            #pragma unroll
            for (int nt = 0; nt < 4; nt++) {
                uint32_t addr = smb + 4 * (W_BHI + (n0 + nt * 8 + bRow) * RS + kw + bHalf);
                ldsm_x2(bh[nt][0], bh[nt][1], addr);
                ldsm_x2(bl[nt][0], bl[nt][1], addr + 4 * (W_BLO - W_BHI));
            }
            #pragma unroll
            for (int mt = 0; mt < 4; mt++)
                #pragma unroll
                for (int nt = 0; nt < 4; nt++) {
                    mma_bf16(acc[mt][nt], ah[mt], bh[nt]);
                    mma_bf16(acc[mt][nt], ah[mt], bl[nt]);
                    mma_bf16(acc[mt][nt], al[mt], bh[nt]);
                }
        }
    }

    const int rr = lane >> 2, cc = (lane & 3) * 2;
    #pragma unroll
    for (int nt = 0; nt < 4; nt++) {
        const int col = col0 + n0 + nt * 8 + cc;
        const float b0 = bias[col], b1 = bias[col + 1];
        #pragma unroll
        for (int mt = 0; mt < 4; mt++) {
            const int row = row0 + m0 + mt * 16 + rr;
            float2 o0 = make_float2(acc[mt][nt][0] + b0, acc[mt][nt][1] + b1);
            float2 o1 = make_float2(acc[mt][nt][2] + b0, acc[mt][nt][3] + b1);
            *reinterpret_cast<float2*>(&C[(size_t)row * DMODEL + col])       = o0;
            *reinterpret_cast<float2*>(&C[(size_t)(row + 8) * DMODEL + col]) = o1;
        }
    }
}

__global__ void __launch_bounds__(256) qkv_tc_kernel(
    const __nv_bfloat16* qxh, const __nv_bfloat16* qxl,
    const __nv_bfloat16* kxh, const __nv_bfloat16* kxl,
    const float* bq, const float* bk, const float* bv,
    float* Q, float* K, float* V)
{
    const int sel = blockIdx.z;
    const __nv_bfloat16* ah = (sel == 0) ? qxh : kxh;
    const __nv_bfloat16* al = (sel == 0) ? qxl : kxl;
    const float* bias = (sel == 0) ? bq : (sel == 1) ? bk : bv;
    float* C = (sel == 0) ? Q : (sel == 1) ? K : V;
    gemm_mma_body(ah, al, g_wt[sel][0], g_wt[sel][1], bias, C);
}

__global__ void __launch_bounds__(256) wo_tc_kernel(
    const __nv_bfloat16* cxh, const __nv_bfloat16* cxl,
    const float* bo, float* X)
{
    gemm_mma_body(cxh, cxl, g_wt[3][0], g_wt[3][1], bo, X);
}

// ---------------- fp32 -> bf16 hi/lo split (elementwise) -------------------
__global__ void split_kernel(const float* __restrict__ x,
                             __nv_bfloat16* __restrict__ hi,
                             __nv_bfloat16* __restrict__ lo)
{
    size_t i = (size_t)blockIdx.x * 256 + threadIdx.x;
    float4 v = reinterpret_cast<const float4*>(x)[i];
    uint32_t h0, l0, h1, l1;
    split2(v.x, v.y, h0, l0);
    split2(v.z, v.w, h1, l1);
    reinterpret_cast<uint32_t*>(hi)[i * 2]     = h0;
    reinterpret_cast<uint32_t*>(hi)[i * 2 + 1] = h1;
    reinterpret_cast<uint32_t*>(lo)[i * 2]     = l0;
    reinterpret_cast<uint32_t*>(lo)[i * 2 + 1] = l1;
}

// ---------------- weight transpose + split: T[n][k] = W[k][n] --------------
__global__ void wt_split_kernel(const float* __restrict__ W,
                                __nv_bfloat16* __restrict__ Thi,
                                __nv_bfloat16* __restrict__ Tlo)
{
    __shared__ float t[32][33];
    const int tx = threadIdx.x, ty = threadIdx.y;
    const int bk0 = blockIdx.y * 32;
    const int bn0 = blockIdx.x * 32;
    #pragma unroll
    for (int j = 0; j < 32; j += 8)
        t[ty + j][tx] = W[(size_t)(bk0 + ty + j) * DMODEL + bn0 + tx];
    __syncthreads();
    #pragma unroll
    for (int j = 0; j < 32; j += 8) {
        float v = t[tx][ty + j];
        size_t o = (size_t)(bn0 + ty + j) * DMODEL + bk0 + tx;
        __nv_bfloat16 h = __float2bfloat16(v);
        Thi[o] = h;
        Tlo[o] = __float2bfloat16(v - __bfloat162float(h));
    }
}

// =============== scores via mma: raw S = Qh@Kh^T/8 + bias, masked ==========
// smem: 4 tiles of 128 rows x 64 bf16, row stride 144B (conflict-free ldsm)
#define SC_T (128 * 144)
__global__ void __launch_bounds__(256) scores_mma_kernel(
    const __nv_bfloat16* __restrict__ Qhi, const __nv_bfloat16* __restrict__ Qlo,
    const __nv_bfloat16* __restrict__ Khi, const __nv_bfloat16* __restrict__ Klo,
    const int* __restrict__ mask_k, const float* __restrict__ log_g,
    float* __restrict__ W)
{
    extern __shared__ char sms[];
    const uint32_t smb = smem_u32_of(sms);
    const int bh = blockIdx.z, b = bh >> 3, h = bh & 7;
    const int q0 = blockIdx.y * 128, k0 = blockIdx.x * 128;
    const int tid = threadIdx.x, wid = tid >> 5, lane = tid & 31;
    const int m0 = (wid >> 2) * 64, n0 = (wid & 3) * 32;

    const __nv_bfloat16* srcs[4] = {
        Qhi + ((size_t)b * NQ + q0) * DMODEL + h * DHEAD,
        Qlo + ((size_t)b * NQ + q0) * DMODEL + h * DHEAD,
        Khi + ((size_t)b * NK + k0) * DMODEL + h * DHEAD,
        Klo + ((size_t)b * NK + k0) * DMODEL + h * DHEAD };
    #pragma unroll
    for (int t = 0; t < 4; t++) {
        #pragma unroll
        for (int i = 0; i < 4; i++) {
            int idx = tid + i * 256;          // 0..1023
            int r = idx >> 3, c = idx & 7;
            uint4 v = *reinterpret_cast<const uint4*>(srcs[t] + (size_t)r * DMODEL + c * 8);
            *reinterpret_cast<uint4*>(sms + t * SC_T + r * 144 + c * 16) = v;
        }
    }
    __syncthreads();

    float acc[4][4][4];
    #pragma unroll
    for (int mt = 0; mt < 4; mt++)
        #pragma unroll
        for (int nt = 0; nt < 4; nt++)
            #pragma unroll
            for (int e = 0; e < 4; e++) acc[mt][nt][e] = 0.f;

    #pragma unroll
    for (int kk = 0; kk < 4; kk++) {
        uint32_t ah[4][4], al[4][4], bh2[4][2], bl2[4][2];
        #pragma unroll
        for (int mt = 0; mt < 4; mt++) {
            uint32_t addr = smb + (m0 + mt * 16 + (lane & 15)) * 144
                          + kk * 32 + ((lane >> 4) << 4);
            ldsm_x4(ah[mt][0], ah[mt][1], ah[mt][2], ah[mt][3], addr);
            ldsm_x4(al[mt][0], al[mt][1], al[mt][2], al[mt][3], addr + SC_T);
        }
        #pragma unroll
        for (int nt = 0; nt < 4; nt++) {
            uint32_t addr = smb + 2 * SC_T + (n0 + nt * 8 + (lane & 7)) * 144
                          + kk * 32 + (((lane >> 3) & 1) << 4);
            ldsm_x2(bh2[nt][0], bh2[nt][1], addr);
            ldsm_x2(bl2[nt][0], bl2[nt][1], addr + SC_T);
        }
        #pragma unroll
        for (int mt = 0; mt < 4; mt++)
            #pragma unroll
            for (int nt = 0; nt < 4; nt++) {
                mma_bf16(acc[mt][nt], ah[mt], bh2[nt]);
                mma_bf16(acc[mt][nt], ah[mt], bl2[nt]);
                mma_bf16(acc[mt][nt], al[mt], bh2[nt]);
            }
    }

    const int rr = lane >> 2, cc = (lane & 3) * 2;
    float* Wbh = W + (size_t)bh * NQ * NK;
    #pragma unroll
    for (int nt = 0; nt < 4; nt++) {
        const int col = k0 + n0 + nt * 8 + cc;
        const float g0 = log_g[b * NK + col], g1 = log_g[b * NK + col + 1];
        const bool  m0b = mask_k[b * NK + col] != 0;
        const bool  m1b = mask_k[b * NK + col + 1] != 0;
        #pragma unroll
        for (int mt = 0; mt < 4; mt++) {
            const int row = q0 + m0 + mt * 16 + rr;
            float2 o0 = make_float2(m0b ? acc[mt][nt][0] * 0.125f + g0 : -INFINITY,
                                    m1b ? acc[mt][nt][1] * 0.125f + g1 : -INFINITY);
            float2 o1 = make_float2(m0b ? acc[mt][nt][2] * 0.125f + g0 : -INFINITY,
                                    m1b ? acc[mt][nt][3] * 0.125f + g1 : -INFINITY);
            *reinterpret_cast<float2*>(&Wbh[(size_t)row * NK + col])       = o0;
            *reinterpret_cast<float2*>(&Wbh[(size_t)(row + 8) * NK + col]) = o1;
        }
    }
}

// ---------------- in-place row softmax over NK=1024 (float4) ---------------
__global__ void softmax_kernel(float* __restrict__ W)
{
    float4* p = reinterpret_cast<float4*>(W + (size_t)blockIdx.x * NK);
    const int tid  = threadIdx.x;
    const int lane = tid & 31, wid = tid >> 5;
    float4 v = p[tid];

    float m = fmaxf(fmaxf(v.x, v.y), fmaxf(v.z, v.w));
    #pragma unroll
    for (int o = 16; o > 0; o >>= 1) m = fmaxf(m, __shfl_xor_sync(~0u, m, o));
    __shared__ float red[8];
    if (lane == 0) red[wid] = m;
    __syncthreads();
    m = red[0];
    #pragma unroll
    for (int i = 1; i < 8; i++) m = fmaxf(m, red[i]);
    __syncthreads();

    v.x = __expf(v.x - m); v.y = __expf(v.y - m);
    v.z = __expf(v.z - m); v.w = __expf(v.w - m);
    float s = v.x + v.y + v.z + v.w;
    #pragma unroll
    for (int o = 16; o > 0; o >>= 1) s += __shfl_xor_sync(~0u, s, o);
    if (lane == 0) red[wid] = s;
    __syncthreads();
    s = red[0];
    #pragma unroll
    for (int i = 1; i < 8; i++) s += red[i];
    float inv = 1.0f / s;
    v.x *= inv; v.y *= inv; v.z *= inv; v.w *= inv;
    p[tid] = v;
}

// =============== ctx via mma: split-K, w and V converted on stage ==========
// smem: w hi/lo 128x32 bf16 (row stride 80B); V hi/lo 32x64 bf16 (stride 144B)
#define CW_HI 0
#define CW_LO (128 * 80)
#define CV_HI (2 * 128 * 80)
#define CV_LO (CV_HI + 32 * 144)
#define CTX_SMEM (CV_LO + 32 * 144)

__global__ void __launch_bounds__(256, 3)
ctx_mma_kernel(const float* __restrict__ W, const float* __restrict__ V,
               float* __restrict__ ctx_part)
{
    __shared__ __align__(16) char smc[CTX_SMEM];
    const uint32_t smb = smem_u32_of(smc);
    const int kc = blockIdx.x;
    const int bh = blockIdx.z, b = bh >> 3, h = bh & 7;
    const int q0 = blockIdx.y * 128;
    const int tid = threadIdx.x, wid = tid >> 5, lane = tid & 31;
    const int m0 = (wid & 3) * 32, n0 = (wid >> 2) * 32;
    const int kbeg = kc * (NK / KSPLIT);

    const float* Wb = W + (size_t)bh * NQ * NK;
    const float* Vb = V + (size_t)b * NK * DMODEL + h * DHEAD;

    float acc[2][4][4];
    #pragma unroll
    for (int mt = 0; mt < 2; mt++)
        #pragma unroll
        for (int nt = 0; nt < 4; nt++)
            #pragma unroll
            for (int e = 0; e < 4; e++) acc[mt][nt][e] = 0.f;

    for (int k0 = kbeg; k0 < kbeg + NK / KSPLIT; k0 += 32) {
        if (k0 != kbeg) __syncthreads();
        // stage w 128x32: each thread converts 16 floats
        {
            const int r = tid >> 1, hf = tid & 1;
            const float* src = Wb + (size_t)(q0 + r) * NK + k0 + hf * 16;
            char* dhi = smc + CW_HI + r * 80 + hf * 32;
            char* dlo = smc + CW_LO + r * 80 + hf * 32;
            #pragma unroll
            for (int j = 0; j < 4; j++) {
                float4 v = *reinterpret_cast<const float4*>(src + j * 4);
                uint32_t h0, l0, h1, l1;
                split2(v.x, v.y, h0, l0);
                split2(v.z, v.w, h1, l1);
                *reinterpret_cast<uint2*>(dhi + j * 8) = make_uint2(h0, h1);
                *reinterpret_cast<uint2*>(dlo + j * 8) = make_uint2(l0, l1);
            }
        }
        // stage V 32x64: 512 float4s, 2 per thread
        #pragma unroll
        for (int i = 0; i < 2; i++) {
            int idx = tid + i * 256;
            int r = idx >> 4, c = idx & 15;
            float4 v = *reinterpret_cast<const float4*>(
                Vb + (size_t)(k0 + r) * DMODEL + c * 4);
            uint32_t h0, l0, h1, l1;
            split2(v.x, v.y, h0, l0);
            split2(v.z, v.w, h1, l1);
            *reinterpret_cast<uint2*>(smc + CV_HI + r * 144 + c * 8) = make_uint2(h0, h1);
            *reinterpret_cast<uint2*>(smc + CV_LO + r * 144 + c * 8) = make_uint2(l0, l1);
        }
        __syncthreads();

        #pragma unroll
        for (int kk = 0; kk < 2; kk++) {
            uint32_t ah[2][4], al[2][4], bh2[4][2], bl2[4][2];
            #pragma unroll
            for (int mt = 0; mt < 2; mt++) {
                uint32_t addr = smb + CW_HI + (m0 + mt * 16 + (lane & 15)) * 80
                              + kk * 32 + ((lane >> 4) << 4);
                ldsm_x4(ah[mt][0], ah[mt][1], ah[mt][2], ah[mt][3], addr);
                ldsm_x4(al[mt][0], al[mt][1], al[mt][2], al[mt][3],
                        addr + (CW_LO - CW_HI));
            }
            #pragma unroll
            for (int nt = 0; nt < 4; nt++) {
                uint32_t addr = smb + CV_HI + (kk * 16 + (lane & 15)) * 144
                              + (n0 + nt * 8) * 2;
                ldsm_x2_trans(bh2[nt][0], bh2[nt][1], addr);
                ldsm_x2_trans(bl2[nt][0], bl2[nt][1], addr + (CV_LO - CV_HI));
            }
            #pragma unroll
            for (int mt = 0; mt < 2; mt++)
                #pragma unroll
                for (int nt = 0; nt < 4; nt++) {
                    mma_bf16(acc[mt][nt], ah[mt], bh2[nt]);
                    mma_bf16(acc[mt][nt], ah[mt], bl2[nt]);
                    mma_bf16(acc[mt][nt], al[mt], bh2[nt]);
                }
        }
    }

    const int rr = lane >> 2, cc = (lane & 3) * 2;
    float* Cp = ctx_part + (size_t)kc * BATCH * NQ * DMODEL
              + (size_t)b * NQ * DMODEL + h * DHEAD;
    #pragma unroll
    for (int mt = 0; mt < 2; mt++) {
        const int row = q0 + m0 + mt * 16 + rr;
        #pragma unroll
        for (int nt = 0; nt < 4; nt++) {
            const int col = n0 + nt * 8 + cc;
            *reinterpret_cast<float2*>(&Cp[(size_t)row * DMODEL + col]) =
                make_float2(acc[mt][nt][0], acc[mt][nt][1]);
            *reinterpret_cast<float2*>(&Cp[(size_t)(row + 8) * DMODEL + col]) =
                make_float2(acc[mt][nt][2], acc[mt][nt][3]);
        }
    }
}

__global__ void ctx_reduce_kernel(const float* __restrict__ part,
                                  float* __restrict__ ctx)
{
    const size_t CE = (size_t)BATCH * NQ * DMODEL;
    size_t i = ((size_t)blockIdx.x * 256 + threadIdx.x) * 4;
    float4 a = *reinterpret_cast<const float4*>(part + i);
    float4 b = *reinterpret_cast<const float4*>(part + CE + i);
    float4 c = *reinterpret_cast<const float4*>(part + 2 * CE + i);
    float4 d = *reinterpret_cast<const float4*>(part + 3 * CE + i);
    *reinterpret_cast<float4*>(ctx + i) =
        make_float4(a.x + b.x + c.x + d.x, a.y + b.y + c.y + d.y,
                    a.z + b.z + c.z + d.z, a.w + b.w + c.w + d.w);
}

__global__ void ln_kernel(const float* __restrict__ x,
                          const float* __restrict__ qx,
                          const float* __restrict__ g,
                          const float* __restrict__ beta,
                          float* __restrict__ out)
{
    const int row = blockIdx.x;
    const int tid = threadIdx.x;
    const float* xr = x  + (size_t)row * DMODEL;
    const float* qr = qx + (size_t)row * DMODEL;

    float v0 = xr[tid]       + qr[tid];
    float v1 = xr[tid + 256] + qr[tid + 256];

    __shared__ float red[256];
    red[tid] = v0 + v1; __syncthreads();
    for (int s = 128; s > 0; s >>= 1) {
        if (tid < s) red[tid] += red[tid + s];
        __syncthreads();
    }
    float mu = red[0] * (1.0f / DMODEL);
    __syncthreads();

    float d0 = v0 - mu, d1 = v1 - mu;
    red[tid] = d0 * d0 + d1 * d1; __syncthreads();
    for (int s = 128; s > 0; s >>= 1) {
        if (tid < s) red[tid] += red[tid + s];
        __syncthreads();
    }
    float rs = rsqrtf(red[0] * (1.0f / DMODEL) + LN_EPS);

    out[(size_t)row * DMODEL + tid]       = d0 * rs * g[tid]       + beta[tid];
    out[(size_t)row * DMODEL + tid + 256] = d1 * rs * g[tid + 256] + beta[tid + 256];
}

// ---------------------------------------------------------------------------
extern "C" void kernel_launch(void* const* d_in, const int* in_sizes, int n_in,
                              void* d_out, int out_size)
{
    const float* qx     = (const float*)d_in[0];
    const float* kx     = (const float*)d_in[1];
    const int*   mask_k = (const int*)d_in[3];     // bool -> int32 in harness
    const float* log_g  = (const float*)d_in[4];
    const float* Wq     = (const float*)d_in[5];
    const float* bq     = (const float*)d_in[6];
    const float* Wk     = (const float*)d_in[7];
    const float* bk     = (const float*)d_in[8];
    const float* Wv     = (const float*)d_in[9];
    const float* bv     = (const float*)d_in[10];
    const float* Wo     = (const float*)d_in[11];
    const float* bo     = (const float*)d_in[12];
    const float* ln_g   = (const float*)d_in[13];
    const float* ln_b   = (const float*)d_in[14];
    (void)in_sizes; (void)n_in;

    float *Qp, *Kp, *Vp, *ctxp, *ctx_part, *xp, *wfb;
    cudaGetSymbolAddress((void**)&Qp,       g_Q);
    cudaGetSymbolAddress((void**)&Kp,       g_K);
    cudaGetSymbolAddress((void**)&Vp,       g_V);
    cudaGetSymbolAddress((void**)&ctxp,     g_ctx);
    cudaGetSymbolAddress((void**)&ctx_part, g_ctx_part);
    cudaGetSymbolAddress((void**)&xp,       g_x);
    cudaGetSymbolAddress((void**)&wfb,      g_w_fb);

    __nv_bfloat16 *qxh, *qxl, *kxh, *kxl, *cxh, *cxl, *wt;
    cudaGetSymbolAddress((void**)&qxh, g_qx_hi);
    cudaGetSymbolAddress((void**)&qxl, g_qx_lo);
    cudaGetSymbolAddress((void**)&kxh, g_kx_hi);
    cudaGetSymbolAddress((void**)&kxl, g_kx_lo);
    cudaGetSymbolAddress((void**)&cxh, g_cx_hi);
    cudaGetSymbolAddress((void**)&cxl, g_cx_lo);
    cudaGetSymbolAddress((void**)&wt,  g_wt);
    const size_t WSTRIDE = (size_t)DMODEL * DMODEL;

    const size_t LN_ELEMS = (size_t)BATCH * NQ * DMODEL;
    const size_t W_ELEMS  = (size_t)BATCH * NHEAD * NQ * NK;
    float* out_ln = (float*)d_out;
    float* Wbuf   = ((size_t)out_size >= LN_ELEMS + W_ELEMS)
                        ? (out_ln + LN_ELEMS) : wfb;

    const int SMEM_SCORES = 4 * SC_T;   // 73728
    cudaFuncSetAttribute(scores_mma_kernel,
                         cudaFuncAttributeMaxDynamicSharedMemorySize, SMEM_SCORES);

    // input splits (fp32 -> bf16 hi/lo)
    const unsigned SPLIT_BLKS = (unsigned)(LN_ELEMS / 4 / 256);
    split_kernel<<<SPLIT_BLKS, 256>>>(qx, qxh, qxl);
    split_kernel<<<SPLIT_BLKS, 256>>>(kx, kxh, kxl);

    // weight transpose + split
    dim3 wtg(16, 16), wtb(32, 8);
    wt_split_kernel<<<wtg, wtb>>>(Wq, wt + 0 * WSTRIDE, wt + 1 * WSTRIDE);
    wt_split_kernel<<<wtg, wtb>>>(Wk, wt + 2 * WSTRIDE, wt + 3 * WSTRIDE);
    wt_split_kernel<<<wtg, wtb>>>(Wv, wt + 4 * WSTRIDE, wt + 5 * WSTRIDE);
    wt_split_kernel<<<wtg, wtb>>>(Wo, wt + 6 * WSTRIDE, wt + 7 * WSTRIDE);

    // Q/K/V projections (mma.sync)
    dim3 gqkv(DMODEL / 128, (BATCH * NQ) / 128, 3);
    qkv_tc_kernel<<<gqkv, 256>>>(qxh, qxl, kxh, kxl, bq, bk, bv, Qp, Kp, Vp);

    // split projected Q, K to bf16 hi/lo (input split buffers are dead now)
    split_kernel<<<SPLIT_BLKS, 256>>>(Qp, qxh, qxl);
    split_kernel<<<SPLIT_BLKS, 256>>>(Kp, kxh, kxl);

    // attention scores on tensor pipe (+bias, +mask), raw fp32 out
    dim3 gsc(NK / 128, NQ / 128, BATCH * NHEAD);
    scores_mma_kernel<<<gsc, 256, SMEM_SCORES>>>(qxh, qxl, kxh, kxl,
                                                 mask_k, log_g, Wbuf);

    // row softmax in place
    softmax_kernel<<<BATCH * NHEAD * NQ, 256>>>(Wbuf);

    // ctx = w @ V per head on tensor pipe, split-K
    dim3 gctx(KSPLIT, NQ / 128, BATCH * NHEAD);
    ctx_mma_kernel<<<gctx, 256>>>(Wbuf, Vp, ctx_part);
    ctx_reduce_kernel<<<(unsigned)(LN_ELEMS / 4 / 256), 256>>>(ctx_part, ctxp);

    // ctx split + output projection (mma.sync)
    split_kernel<<<SPLIT_BLKS, 256>>>(ctxp, cxh, cxl);
    dim3 go(DMODEL / 128, (BATCH * NQ) / 128);
    wo_tc_kernel<<<go, 256>>>(cxh, cxl, bo, xp);

    // residual + LayerNorm
    ln_kernel<<<BATCH * NQ, 256>>>(xp, qx, ln_g, ln_b, out_ln);
}

// round 16
// speedup vs baseline: 1.0063x; 1.0063x over previous
#include <cuda_runtime.h>
#include <cuda_bf16.h>
#include <math.h>
#include <stdint.h>

#define BATCH  4
#define NQ     1024
#define NK     1024
#define DMODEL 512
#define NHEAD  8
#define DHEAD  64
#define LN_EPS 1e-5f

#define KSPLIT 4  // ctx split-K factor

// ---------------- scratch (device globals: allocation-free) ----------------
__device__ float g_Q[(size_t)BATCH * NQ * DMODEL];
__device__ float g_K[(size_t)BATCH * NK * DMODEL];
__device__ float g_V[(size_t)BATCH * NK * DMODEL];
__device__ float g_ctx[(size_t)BATCH * NQ * DMODEL];
__device__ float g_ctx_part[(size_t)KSPLIT * BATCH * NQ * DMODEL];
__device__ float g_x[(size_t)BATCH * NQ * DMODEL];
__device__ float g_w_fb[(size_t)BATCH * NHEAD * NQ * NK];

// bf16 hi/lo split buffers (reused: input split -> then Q/K split)
__device__ __align__(256) __nv_bfloat16 g_qx_hi[(size_t)BATCH * NQ * DMODEL];
__device__ __align__(256) __nv_bfloat16 g_qx_lo[(size_t)BATCH * NQ * DMODEL];
__device__ __align__(256) __nv_bfloat16 g_kx_hi[(size_t)BATCH * NK * DMODEL];
__device__ __align__(256) __nv_bfloat16 g_kx_lo[(size_t)BATCH * NK * DMODEL];
__device__ __align__(256) __nv_bfloat16 g_cx_hi[(size_t)BATCH * NQ * DMODEL];
__device__ __align__(256) __nv_bfloat16 g_cx_lo[(size_t)BATCH * NQ * DMODEL];
// transposed+split weights: [mat 0..3 = q,k,v,o][hi=0,lo=1][N=512][K=512]
__device__ __align__(256) __nv_bfloat16 g_wt[4][2][(size_t)DMODEL * DMODEL];

// ================= warp-MMA primitives (base ISA) ==========================
__device__ __forceinline__ uint32_t smem_u32_of(const void* p) {
    uint32_t a;
    asm("{ .reg .u64 t; cvta.to.shared.u64 t, %1; cvt.u32.u64 %0, t; }"
        : "=r"(a) : "l"(p));
    return a;
}
__device__ __forceinline__ void ldsm_x4(uint32_t& r0, uint32_t& r1,
                                        uint32_t& r2, uint32_t& r3, uint32_t a) {
    asm volatile("ldmatrix.sync.aligned.m8n8.x4.shared.b16 {%0,%1,%2,%3}, [%4];"
                 : "=r"(r0), "=r"(r1), "=r"(r2), "=r"(r3) : "r"(a));
}
__device__ __forceinline__ void ldsm_x2(uint32_t& r0, uint32_t& r1, uint32_t a) {
    asm volatile("ldmatrix.sync.aligned.m8n8.x2.shared.b16 {%0,%1}, [%2];"
                 : "=r"(r0), "=r"(r1) : "r"(a));
}
__device__ __forceinline__ void ldsm_x2_trans(uint32_t& r0, uint32_t& r1, uint32_t a) {
    asm volatile("ldmatrix.sync.aligned.m8n8.x2.trans.shared.b16 {%0,%1}, [%2];"
                 : "=r"(r0), "=r"(r1) : "r"(a));
}
__device__ __forceinline__ void mma_bf16(float* c, const uint32_t* a, const uint32_t* b) {
    asm volatile(
        "mma.sync.aligned.m16n8k16.row.col.f32.bf16.bf16.f32 "
        "{%0,%1,%2,%3}, {%4,%5,%6,%7}, {%8,%9}, {%0,%1,%2,%3};"
        : "+f"(c[0]), "+f"(c[1]), "+f"(c[2]), "+f"(c[3])
        : "r"(a[0]), "r"(a[1]), "r"(a[2]), "r"(a[3]), "r"(b[0]), "r"(b[1]));
}
__device__ __forceinline__ uint32_t pack_bf2(__nv_bfloat16 x, __nv_bfloat16 y) {
    return (uint32_t)__bfloat16_as_ushort(x) |
           ((uint32_t)__bfloat16_as_ushort(y) << 16);
}
__device__ __forceinline__ void split2(float x, float y, uint32_t& hi, uint32_t& lo) {
    __nv_bfloat16 hx = __float2bfloat16(x), hy = __float2bfloat16(y);
    __nv_bfloat16 lx = __float2bfloat16(x - __bfloat162float(hx));
    __nv_bfloat16 ly = __float2bfloat16(y - __bfloat162float(hy));
    hi = pack_bf2(hx, hy);
    lo = pack_bf2(lx, ly);
}

// ============== projection GEMM (unchanged from R10) =======================
#define RS    20
#define W_AHI 0
#define W_ALO (128 * RS)
#define W_BHI (2 * 128 * RS)
#define W_BLO (3 * 128 * RS)

__device__ __forceinline__ void gemm_mma_body(
    const __nv_bfloat16* __restrict__ Ahi, const __nv_bfloat16* __restrict__ Alo,
    const __nv_bfloat16* __restrict__ Bhi, const __nv_bfloat16* __restrict__ Blo,
    const float* __restrict__ bias, float* __restrict__ C)
{
    __shared__ uint32_t smw[4 * 128 * RS];
    const uint32_t smb = smem_u32_of(smw);
    const int tid  = threadIdx.x;
    const int wid  = tid >> 5, lane = tid & 31;
    const int row0 = blockIdx.y * 128;
    const int col0 = blockIdx.x * 128;
    const int m0   = (wid >> 2) * 64;
    const int n0   = (wid & 3) * 32;

    const int aRow  = lane & 15;
    const int aHalf = (lane >> 4) << 2;
    const int bRow  = lane & 7;
    const int bHalf = ((lane >> 3) & 1) << 2;

    float acc[4][4][4];
    #pragma unroll
    for (int mt = 0; mt < 4; mt++)
        #pragma unroll
        for (int nt = 0; nt < 4; nt++)
            #pragma unroll
            for (int e = 0; e < 4; e++) acc[mt][nt][e] = 0.f;

    for (int ks = 0; ks < DMODEL; ks += 32) {
        if (ks) __syncthreads();
        #pragma unroll
        for (int i = 0; i < 2; i++) {
            int idx = tid + i * 256;
            int r = idx >> 2, c = idx & 3;
            *reinterpret_cast<uint4*>(&smw[W_AHI + r * RS + c * 4]) =
                *reinterpret_cast<const uint4*>(Ahi + (size_t)(row0 + r) * DMODEL + ks + c * 8);
            *reinterpret_cast<uint4*>(&smw[W_ALO + r * RS + c * 4]) =
                *reinterpret_cast<const uint4*>(Alo + (size_t)(row0 + r) * DMODEL + ks + c * 8);
            *reinterpret_cast<uint4*>(&smw[W_BHI + r * RS + c * 4]) =
                *reinterpret_cast<const uint4*>(Bhi + (size_t)(col0 + r) * DMODEL + ks + c * 8);
            *reinterpret_cast<uint4*>(&smw[W_BLO + r * RS + c * 4]) =
                *reinterpret_cast<const uint4*>(Blo + (size_t)(col0 + r) * DMODEL + ks + c * 8);
        }
        __syncthreads();

        #pragma unroll
        for (int kk = 0; kk < 2; kk++) {
            const int kw = kk * 8;
            uint32_t ah[4][4], al[4][4], bh[4][2], bl[4][2];
            #pragma unroll
            for (int mt = 0; mt < 4; mt++) {
                uint32_t addr = smb + 4 * (W_AHI + (m0 + mt * 16 + aRow) * RS + kw + aHalf);
                ldsm_x4(ah[mt][0], ah[mt][1], ah[mt][2], ah[mt][3], addr);
                ldsm_x4(al[mt][0], al[mt][1], al[mt][2], al[mt][3],
                        addr + 4 * (W_ALO - W_AHI));
            }
            #pragma unroll
            for (int nt = 0; nt < 4; nt++) {
                uint32_t addr = smb + 4 * (W_BHI + (n0 + nt * 8 + bRow) * RS + kw + bHalf);
                ldsm_x2(bh[nt][0], bh[nt][1], addr);
                ldsm_x2(bl[nt][0], bl[nt][1], addr + 4 * (W_BLO - W_BHI));
            }
            #pragma unroll
            for (int mt = 0; mt < 4; mt++)
                #pragma unroll
                for (int nt = 0; nt < 4; nt++) {
                    mma_bf16(acc[mt][nt], ah[mt], bh[nt]);
                    mma_bf16(acc[mt][nt], ah[mt], bl[nt]);
                    mma_bf16(acc[mt][nt], al[mt], bh[nt]);
                }
        }
    }

    const int rr = lane >> 2, cc = (lane & 3) * 2;
    #pragma unroll
    for (int nt = 0; nt < 4; nt++) {
        const int col = col0 + n0 + nt * 8 + cc;
        const float b0 = bias[col], b1 = bias[col + 1];
        #pragma unroll
        for (int mt = 0; mt < 4; mt++) {
            const int row = row0 + m0 + mt * 16 + rr;
            float2 o0 = make_float2(acc[mt][nt][0] + b0, acc[mt][nt][1] + b1);
            float2 o1 = make_float2(acc[mt][nt][2] + b0, acc[mt][nt][3] + b1);
            *reinterpret_cast<float2*>(&C[(size_t)row * DMODEL + col])       = o0;
            *reinterpret_cast<float2*>(&C[(size_t)(row + 8) * DMODEL + col]) = o1;
        }
    }
}

__global__ void __launch_bounds__(256) qkv_tc_kernel(
    const __nv_bfloat16* qxh, const __nv_bfloat16* qxl,
    const __nv_bfloat16* kxh, const __nv_bfloat16* kxl,
    const float* bq, const float* bk, const float* bv,
    float* Q, float* K, float* V)
{
    const int sel = blockIdx.z;
    const __nv_bfloat16* ah = (sel == 0) ? qxh : kxh;
    const __nv_bfloat16* al = (sel == 0) ? qxl : kxl;
    const float* bias = (sel == 0) ? bq : (sel == 1) ? bk : bv;
    float* C = (sel == 0) ? Q : (sel == 1) ? K : V;
    gemm_mma_body(ah, al, g_wt[sel][0], g_wt[sel][1], bias, C);
}

__global__ void __launch_bounds__(256) wo_tc_kernel(
    const __nv_bfloat16* cxh, const __nv_bfloat16* cxl,
    const float* bo, float* X)
{
    gemm_mma_body(cxh, cxl, g_wt[3][0], g_wt[3][1], bo, X);
}

// ---------------- fp32 -> bf16 hi/lo split (elementwise) -------------------
__global__ void split_kernel(const float* __restrict__ x,
                             __nv_bfloat16* __restrict__ hi,
                             __nv_bfloat16* __restrict__ lo)
{
    size_t i = (size_t)blockIdx.x * 256 + threadIdx.x;
    float4 v = reinterpret_cast<const float4*>(x)[i];
    uint32_t h0, l0, h1, l1;
    split2(v.x, v.y, h0, l0);
    split2(v.z, v.w, h1, l1);
    reinterpret_cast<uint32_t*>(hi)[i * 2]     = h0;
    reinterpret_cast<uint32_t*>(hi)[i * 2 + 1] = h1;
    reinterpret_cast<uint32_t*>(lo)[i * 2]     = l0;
    reinterpret_cast<uint32_t*>(lo)[i * 2 + 1] = l1;
}

// ---------------- weight transpose + split: T[n][k] = W[k][n] --------------
__global__ void wt_split_kernel(const float* __restrict__ W,
                                __nv_bfloat16* __restrict__ Thi,
                                __nv_bfloat16* __restrict__ Tlo)
{
    __shared__ float t[32][33];
    const int tx = threadIdx.x, ty = threadIdx.y;
    const int bk0 = blockIdx.y * 32;
    const int bn0 = blockIdx.x * 32;
    #pragma unroll
    for (int j = 0; j < 32; j += 8)
        t[ty + j][tx] = W[(size_t)(bk0 + ty + j) * DMODEL + bn0 + tx];
    __syncthreads();
    #pragma unroll
    for (int j = 0; j < 32; j += 8) {
        float v = t[tx][ty + j];
        size_t o = (size_t)(bn0 + ty + j) * DMODEL + bk0 + tx;
        __nv_bfloat16 h = __float2bfloat16(v);
        Thi[o] = h;
        Tlo[o] = __float2bfloat16(v - __bfloat162float(h));
    }
}

// =============== scores via mma: raw S = Qh@Kh^T/8 + bias, masked ==========
// smem: 4 tiles of 128 rows x 64 bf16, row stride 144B (conflict-free ldsm)
#define SC_T (128 * 144)
__global__ void __launch_bounds__(256) scores_mma_kernel(
    const __nv_bfloat16* __restrict__ Qhi, const __nv_bfloat16* __restrict__ Qlo,
    const __nv_bfloat16* __restrict__ Khi, const __nv_bfloat16* __restrict__ Klo,
    const int* __restrict__ mask_k, const float* __restrict__ log_g,
    float* __restrict__ W)
{
    extern __shared__ char sms[];
    const uint32_t smb = smem_u32_of(sms);
    const int bh = blockIdx.z, b = bh >> 3, h = bh & 7;
    const int q0 = blockIdx.y * 128, k0 = blockIdx.x * 128;
    const int tid = threadIdx.x, wid = tid >> 5, lane = tid & 31;
    const int m0 = (wid >> 2) * 64, n0 = (wid & 3) * 32;

    const __nv_bfloat16* srcs[4] = {
        Qhi + ((size_t)b * NQ + q0) * DMODEL + h * DHEAD,
        Qlo + ((size_t)b * NQ + q0) * DMODEL + h * DHEAD,
        Khi + ((size_t)b * NK + k0) * DMODEL + h * DHEAD,
        Klo + ((size_t)b * NK + k0) * DMODEL + h * DHEAD };
    #pragma unroll
    for (int t = 0; t < 4; t++) {
        #pragma unroll
        for (int i = 0; i < 4; i++) {
            int idx = tid + i * 256;          // 0..1023
            int r = idx >> 3, c = idx & 7;
            uint4 v = *reinterpret_cast<const uint4*>(srcs[t] + (size_t)r * DMODEL + c * 8);
            *reinterpret_cast<uint4*>(sms + t * SC_T + r * 144 + c * 16) = v;
        }
    }
    __syncthreads();

    float acc[4][4][4];
    #pragma unroll
    for (int mt = 0; mt < 4; mt++)
        #pragma unroll
        for (int nt = 0; nt < 4; nt++)
            #pragma unroll
            for (int e = 0; e < 4; e++) acc[mt][nt][e] = 0.f;

    #pragma unroll
    for (int kk = 0; kk < 4; kk++) {
        uint32_t ah[4][4], al[4][4], bh2[4][2], bl2[4][2];
        #pragma unroll
        for (int mt = 0; mt < 4; mt++) {
            uint32_t addr = smb + (m0 + mt * 16 + (lane & 15)) * 144
                          + kk * 32 + ((lane >> 4) << 4);
            ldsm_x4(ah[mt][0], ah[mt][1], ah[mt][2], ah[mt][3], addr);
            ldsm_x4(al[mt][0], al[mt][1], al[mt][2], al[mt][3], addr + SC_T);
        }
        #pragma unroll
        for (int nt = 0; nt < 4; nt++) {
            uint32_t addr = smb + 2 * SC_T + (n0 + nt * 8 + (lane & 7)) * 144
                          + kk * 32 + (((lane >> 3) & 1) << 4);
            ldsm_x2(bh2[nt][0], bh2[nt][1], addr);
            ldsm_x2(bl2[nt][0], bl2[nt][1], addr + SC_T);
        }
        #pragma unroll
        for (int mt = 0; mt < 4; mt++)
            #pragma unroll
            for (int nt = 0; nt < 4; nt++) {
                mma_bf16(acc[mt][nt], ah[mt], bh2[nt]);
                mma_bf16(acc[mt][nt], ah[mt], bl2[nt]);
                mma_bf16(acc[mt][nt], al[mt], bh2[nt]);
            }
    }

    const int rr = lane >> 2, cc = (lane & 3) * 2;
    float* Wbh = W + (size_t)bh * NQ * NK;
    #pragma unroll
    for (int nt = 0; nt < 4; nt++) {
        const int col = k0 + n0 + nt * 8 + cc;
        const float g0 = log_g[b * NK + col], g1 = log_g[b * NK + col + 1];
        const bool  m0b = mask_k[b * NK + col] != 0;
        const bool  m1b = mask_k[b * NK + col + 1] != 0;
        #pragma unroll
        for (int mt = 0; mt < 4; mt++) {
            const int row = q0 + m0 + mt * 16 + rr;
            float2 o0 = make_float2(m0b ? acc[mt][nt][0] * 0.125f + g0 : -INFINITY,
                                    m1b ? acc[mt][nt][1] * 0.125f + g1 : -INFINITY);
            float2 o1 = make_float2(m0b ? acc[mt][nt][2] * 0.125f + g0 : -INFINITY,
                                    m1b ? acc[mt][nt][3] * 0.125f + g1 : -INFINITY);
            *reinterpret_cast<float2*>(&Wbh[(size_t)row * NK + col])       = o0;
            *reinterpret_cast<float2*>(&Wbh[(size_t)(row + 8) * NK + col]) = o1;
        }
    }
}

// ---------------- in-place row softmax over NK=1024 (float4) ---------------
__global__ void softmax_kernel(float* __restrict__ W)
{
    float4* p = reinterpret_cast<float4*>(W + (size_t)blockIdx.x * NK);
    const int tid  = threadIdx.x;
    const int lane = tid & 31, wid = tid >> 5;
    float4 v = p[tid];

    float m = fmaxf(fmaxf(v.x, v.y), fmaxf(v.z, v.w));
    #pragma unroll
    for (int o = 16; o > 0; o >>= 1) m = fmaxf(m, __shfl_xor_sync(~0u, m, o));
    __shared__ float red[8];
    if (lane == 0) red[wid] = m;
    __syncthreads();
    m = red[0];
    #pragma unroll
    for (int i = 1; i < 8; i++) m = fmaxf(m, red[i]);
    __syncthreads();

    v.x = __expf(v.x - m); v.y = __expf(v.y - m);
    v.z = __expf(v.z - m); v.w = __expf(v.w - m);
    float s = v.x + v.y + v.z + v.w;
    #pragma unroll
    for (int o = 16; o > 0; o >>= 1) s += __shfl_xor_sync(~0u, s, o);
    if (lane == 0) red[wid] = s;
    __syncthreads();
    s = red[0];
    #pragma unroll
    for (int i = 1; i < 8; i++) s += red[i];
    float inv = 1.0f / s;
    v.x *= inv; v.y *= inv; v.z *= inv; v.w *= inv;
    p[tid] = v;
}

// =============== ctx via mma: split-K, w and V converted on stage ==========
// smem: w hi/lo 128x32 bf16 (row stride 80B); V hi/lo 32x64 bf16 (stride 144B)
#define CW_HI 0
#define CW_LO (128 * 80)
#define CV_HI (2 * 128 * 80)
#define CV_LO (CV_HI + 32 * 144)
#define CTX_SMEM (CV_LO + 32 * 144)

__global__ void __launch_bounds__(256, 3)
ctx_mma_kernel(const float* __restrict__ W, const float* __restrict__ V,
               float* __restrict__ ctx_part)
{
    __shared__ __align__(16) char smc[CTX_SMEM];
    const uint32_t smb = smem_u32_of(smc);
    const int kc = blockIdx.x;
    const int bh = blockIdx.z, b = bh >> 3, h = bh & 7;
    const int q0 = blockIdx.y * 128;
    const int tid = threadIdx.x, wid = tid >> 5, lane = tid & 31;
    const int m0 = (wid & 3) * 32, n0 = (wid >> 2) * 32;
    const int kbeg = kc * (NK / KSPLIT);

    const float* Wb = W + (size_t)bh * NQ * NK;
    const float* Vb = V + (size_t)b * NK * DMODEL + h * DHEAD;

    float acc[2][4][4];
    #pragma unroll
    for (int mt = 0; mt < 2; mt++)
        #pragma unroll
        for (int nt = 0; nt < 4; nt++)
            #pragma unroll
            for (int e = 0; e < 4; e++) acc[mt][nt][e] = 0.f;

    for (int k0 = kbeg; k0 < kbeg + NK / KSPLIT; k0 += 32) {
        if (k0 != kbeg) __syncthreads();
        // stage w 128x32: each thread converts 16 floats
        {
            const int r = tid >> 1, hf = tid & 1;
            const float* src = Wb + (size_t)(q0 + r) * NK + k0 + hf * 16;
            char* dhi = smc + CW_HI + r * 80 + hf * 32;
            char* dlo = smc + CW_LO + r * 80 + hf * 32;
            #pragma unroll
            for (int j = 0; j < 4; j++) {
                float4 v = *reinterpret_cast<const float4*>(src + j * 4);
                uint32_t h0, l0, h1, l1;
                split2(v.x, v.y, h0, l0);
                split2(v.z, v.w, h1, l1);
                *reinterpret_cast<uint2*>(dhi + j * 8) = make_uint2(h0, h1);
                *reinterpret_cast<uint2*>(dlo + j * 8) = make_uint2(l0, l1);
            }
        }
        // stage V 32x64: 512 float4s, 2 per thread
        #pragma unroll
        for (int i = 0; i < 2; i++) {
            int idx = tid + i * 256;
            int r = idx >> 4, c = idx & 15;
            float4 v = *reinterpret_cast<const float4*>(
                Vb + (size_t)(k0 + r) * DMODEL + c * 4);
            uint32_t h0, l0, h1, l1;
            split2(v.x, v.y, h0, l0);
            split2(v.z, v.w, h1, l1);
            *reinterpret_cast<uint2*>(smc + CV_HI + r * 144 + c * 8) = make_uint2(h0, h1);
            *reinterpret_cast<uint2*>(smc + CV_LO + r * 144 + c * 8) = make_uint2(l0, l1);
        }
        __syncthreads();

        #pragma unroll
        for (int kk = 0; kk < 2; kk++) {
            uint32_t ah[2][4], al[2][4], bh2[4][2], bl2[4][2];
            #pragma unroll
            for (int mt = 0; mt < 2; mt++) {
                uint32_t addr = smb + CW_HI + (m0 + mt * 16 + (lane & 15)) * 80
                              + kk * 32 + ((lane >> 4) << 4);
                ldsm_x4(ah[mt][0], ah[mt][1], ah[mt][2], ah[mt][3], addr);
                ldsm_x4(al[mt][0], al[mt][1], al[mt][2], al[mt][3],
                        addr + (CW_LO - CW_HI));
            }
            #pragma unroll
            for (int nt = 0; nt < 4; nt++) {
                uint32_t addr = smb + CV_HI + (kk * 16 + (lane & 15)) * 144
                              + (n0 + nt * 8) * 2;
                ldsm_x2_trans(bh2[nt][0], bh2[nt][1], addr);
                ldsm_x2_trans(bl2[nt][0], bl2[nt][1], addr + (CV_LO - CV_HI));
            }
            #pragma unroll
            for (int mt = 0; mt < 2; mt++)
                #pragma unroll
                for (int nt = 0; nt < 4; nt++) {
                    mma_bf16(acc[mt][nt], ah[mt], bh2[nt]);
                    mma_bf16(acc[mt][nt], ah[mt], bl2[nt]);
                    mma_bf16(acc[mt][nt], al[mt], bh2[nt]);
                }
        }
    }

    const int rr = lane >> 2, cc = (lane & 3) * 2;
    float* Cp = ctx_part + (size_t)kc * BATCH * NQ * DMODEL
              + (size_t)b * NQ * DMODEL + h * DHEAD;
    #pragma unroll
    for (int mt = 0; mt < 2; mt++) {
        const int row = q0 + m0 + mt * 16 + rr;
        #pragma unroll
        for (int nt = 0; nt < 4; nt++) {
            const int col = n0 + nt * 8 + cc;
            *reinterpret_cast<float2*>(&Cp[(size_t)row * DMODEL + col]) =
                make_float2(acc[mt][nt][0], acc[mt][nt][1]);
            *reinterpret_cast<float2*>(&Cp[(size_t)(row + 8) * DMODEL + col]) =
                make_float2(acc[mt][nt][2], acc[mt][nt][3]);
        }
    }
}

__global__ void ctx_reduce_kernel(const float* __restrict__ part,
                                  float* __restrict__ ctx)
{
    const size_t CE = (size_t)BATCH * NQ * DMODEL;
    size_t i = ((size_t)blockIdx.x * 256 + threadIdx.x) * 4;
    float4 a = *reinterpret_cast<const float4*>(part + i);
    float4 b = *reinterpret_cast<const float4*>(part + CE + i);
    float4 c = *reinterpret_cast<const float4*>(part + 2 * CE + i);
    float4 d = *reinterpret_cast<const float4*>(part + 3 * CE + i);
    *reinterpret_cast<float4*>(ctx + i) =
        make_float4(a.x + b.x + c.x + d.x, a.y + b.y + c.y + d.y,
                    a.z + b.z + c.z + d.z, a.w + b.w + c.w + d.w);
}

__global__ void ln_kernel(const float* __restrict__ x,
                          const float* __restrict__ qx,
                          const float* __restrict__ g,
                          const float* __restrict__ beta,
                          float* __restrict__ out)
{
    const int row = blockIdx.x;
    const int tid = threadIdx.x;
    const float* xr = x  + (size_t)row * DMODEL;
    const float* qr = qx + (size_t)row * DMODEL;

    float v0 = xr[tid]       + qr[tid];
    float v1 = xr[tid + 256] + qr[tid + 256];

    __shared__ float red[256];
    red[tid] = v0 + v1; __syncthreads();
    for (int s = 128; s > 0; s >>= 1) {
        if (tid < s) red[tid] += red[tid + s];
        __syncthreads();
    }
    float mu = red[0] * (1.0f / DMODEL);
    __syncthreads();

    float d0 = v0 - mu, d1 = v1 - mu;
    red[tid] = d0 * d0 + d1 * d1; __syncthreads();
    for (int s = 128; s > 0; s >>= 1) {
        if (tid < s) red[tid] += red[tid + s];
        __syncthreads();
    }
    float rs = rsqrtf(red[0] * (1.0f / DMODEL) + LN_EPS);

    out[(size_t)row * DMODEL + tid]       = d0 * rs * g[tid]       + beta[tid];
    out[(size_t)row * DMODEL + tid + 256] = d1 * rs * g[tid + 256] + beta[tid + 256];
}

// ---------------------------------------------------------------------------
extern "C" void kernel_launch(void* const* d_in, const int* in_sizes, int n_in,
                              void* d_out, int out_size)
{
    const float* qx     = (const float*)d_in[0];
    const float* kx     = (const float*)d_in[1];
    const int*   mask_k = (const int*)d_in[3];     // bool -> int32 in harness
    const float* log_g  = (const float*)d_in[4];
    const float* Wq     = (const float*)d_in[5];
    const float* bq     = (const float*)d_in[6];
    const float* Wk     = (const float*)d_in[7];
    const float* bk     = (const float*)d_in[8];
    const float* Wv     = (const float*)d_in[9];
    const float* bv     = (const float*)d_in[10];
    const float* Wo     = (const float*)d_in[11];
    const float* bo     = (const float*)d_in[12];
    const float* ln_g   = (const float*)d_in[13];
    const float* ln_b   = (const float*)d_in[14];
    (void)in_sizes; (void)n_in;

    float *Qp, *Kp, *Vp, *ctxp, *ctx_part, *xp, *wfb;
    cudaGetSymbolAddress((void**)&Qp,       g_Q);
    cudaGetSymbolAddress((void**)&Kp,       g_K);
    cudaGetSymbolAddress((void**)&Vp,       g_V);
    cudaGetSymbolAddress((void**)&ctxp,     g_ctx);
    cudaGetSymbolAddress((void**)&ctx_part, g_ctx_part);
    cudaGetSymbolAddress((void**)&xp,       g_x);
    cudaGetSymbolAddress((void**)&wfb,      g_w_fb);

    __nv_bfloat16 *qxh, *qxl, *kxh, *kxl, *cxh, *cxl, *wt;
    cudaGetSymbolAddress((void**)&qxh, g_qx_hi);
    cudaGetSymbolAddress((void**)&qxl, g_qx_lo);
    cudaGetSymbolAddress((void**)&kxh, g_kx_hi);
    cudaGetSymbolAddress((void**)&kxl, g_kx_lo);
    cudaGetSymbolAddress((void**)&cxh, g_cx_hi);
    cudaGetSymbolAddress((void**)&cxl, g_cx_lo);
    cudaGetSymbolAddress((void**)&wt,  g_wt);
    const size_t WSTRIDE = (size_t)DMODEL * DMODEL;

    const size_t LN_ELEMS = (size_t)BATCH * NQ * DMODEL;
    const size_t W_ELEMS  = (size_t)BATCH * NHEAD * NQ * NK;
    float* out_ln = (float*)d_out;
    float* Wbuf   = ((size_t)out_size >= LN_ELEMS + W_ELEMS)
                        ? (out_ln + LN_ELEMS) : wfb;

    const int SMEM_SCORES = 4 * SC_T;   // 73728
    cudaFuncSetAttribute(scores_mma_kernel,
                         cudaFuncAttributeMaxDynamicSharedMemorySize, SMEM_SCORES);

    // input splits (fp32 -> bf16 hi/lo)
    const unsigned SPLIT_BLKS = (unsigned)(LN_ELEMS / 4 / 256);
    split_kernel<<<SPLIT_BLKS, 256>>>(qx, qxh, qxl);
    split_kernel<<<SPLIT_BLKS, 256>>>(kx, kxh, kxl);

    // weight transpose + split
    dim3 wtg(16, 16), wtb(32, 8);
    wt_split_kernel<<<wtg, wtb>>>(Wq, wt + 0 * WSTRIDE, wt + 1 * WSTRIDE);
    wt_split_kernel<<<wtg, wtb>>>(Wk, wt + 2 * WSTRIDE, wt + 3 * WSTRIDE);
    wt_split_kernel<<<wtg, wtb>>>(Wv, wt + 4 * WSTRIDE, wt + 5 * WSTRIDE);
    wt_split_kernel<<<wtg, wtb>>>(Wo, wt + 6 * WSTRIDE, wt + 7 * WSTRIDE);

    // Q/K/V projections (mma.sync)
    dim3 gqkv(DMODEL / 128, (BATCH * NQ) / 128, 3);
    qkv_tc_kernel<<<gqkv, 256>>>(qxh, qxl, kxh, kxl, bq, bk, bv, Qp, Kp, Vp);

    // split projected Q, K to bf16 hi/lo (input split buffers are dead now)
    split_kernel<<<SPLIT_BLKS, 256>>>(Qp, qxh, qxl);
    split_kernel<<<SPLIT_BLKS, 256>>>(Kp, kxh, kxl);

    // attention scores on tensor pipe (+bias, +mask), raw fp32 out
    dim3 gsc(NK / 128, NQ / 128, BATCH * NHEAD);
    scores_mma_kernel<<<gsc, 256, SMEM_SCORES>>>(qxh, qxl, kxh, kxl,
                                                 mask_k, log_g, Wbuf);

    // row softmax in place
    softmax_kernel<<<BATCH * NHEAD * NQ, 256>>>(Wbuf);

    // ctx = w @ V per head on tensor pipe, split-K
    dim3 gctx(KSPLIT, NQ / 128, BATCH * NHEAD);
    ctx_mma_kernel<<<gctx, 256>>>(Wbuf, Vp, ctx_part);
    ctx_reduce_kernel<<<(unsigned)(LN_ELEMS / 4 / 256), 256>>>(ctx_part, ctxp);

    // ctx split + output projection (mma.sync)
    split_kernel<<<SPLIT_BLKS, 256>>>(ctxp, cxh, cxl);
    dim3 go(DMODEL / 128, (BATCH * NQ) / 128);
    wo_tc_kernel<<<go, 256>>>(cxh, cxl, bo, xp);

    // residual + LayerNorm
    ln_kernel<<<BATCH * NQ, 256>>>(xp, qx, ln_g, ln_b, out_ln);
}